// round 14
// baseline (speedup 1.0000x reference)
#include <cuda_runtime.h>
#include <cstdint>

// PytorchLUTFakeQuant: t = clip(x*64, -128, 127); nearest of 16 sorted
// INTEGER centers (tie -> lower index); out = center / 64.
//
// 511-entry shared LUT indexed by ceil(clip(x*128, -256, 254)) + 256.
// (ceil-count identity reproduces argmin lower-index tie-break exactly;
// verified rel_err = 0.)
//
// Round 14: cp.async SMEM pipeline. R10/R13 proved register-held MLP
// costs occupancy 1:1. cp.async holds in-flight bytes in SMEM instead:
// 4 stages x 8KB committed up front (128B/thread in flight at ~30 regs),
// consumed stage-by-stage with per-thread wait_group (each thread reads
// only bytes it copied -> zero barriers in the loop). BLOCK=256, 34KB
// smem -> 6 blocks/SM (48 warps). Kept: L2::evict_last on x (cache_hint),
// discard-before-store on out, STG.256, exact grid 1568.

static constexpr int NC = 16;
static constexpr int LUT_SIZE = 512;
static constexpr int BLOCK = 256;
static constexpr int STAGES = 4;
// stage = BLOCK threads * 32B = 8KB = 512 float4; block work = 32KB.
static constexpr int STAGE_F4 = BLOCK * 2;              // 512 float4
static constexpr int BLOCK_F4 = STAGES * STAGE_F4;      // 2048 float4

__device__ __forceinline__ void cp16(uint32_t dst_smem, const void* src,
                                     uint64_t pol) {
    asm volatile("cp.async.cg.shared.global.L2::cache_hint [%0], [%1], 16, %2;"
                 :: "r"(dst_smem), "l"(src), "l"(pol) : "memory");
}

template <int N>
__device__ __forceinline__ void cp_wait() {
    asm volatile("cp.async.wait_group %0;" :: "n"(N) : "memory");
}

__device__ __forceinline__ void stg_256(float4* p, float4 a, float4 b) {
    asm volatile("st.global.v8.b32 [%0], {%1,%2,%3,%4,%5,%6,%7,%8};"
                 :: "l"(p),
                    "r"(__float_as_uint(a.x)), "r"(__float_as_uint(a.y)),
                    "r"(__float_as_uint(a.z)), "r"(__float_as_uint(a.w)),
                    "r"(__float_as_uint(b.x)), "r"(__float_as_uint(b.y)),
                    "r"(__float_as_uint(b.z)), "r"(__float_as_uint(b.w))
                 : "memory");
}

__global__ void __launch_bounds__(BLOCK, 6)
lut_fakequant_kernel(const float4* __restrict__ x,
                     const float* __restrict__ centers,
                     float4* __restrict__ out) {
    __shared__ float lut[LUT_SIZE];
    __shared__ float4 buf[BLOCK_F4];          // 32KB staging

    // ---- Build LUT: lut[k] = cv[ #{ m_i <= k-257 } ] / 64 (2/thread) ----
    {
        const float4* c4 = (const float4*)centers;
        float4 g0 = __ldg(c4 + 0), g1 = __ldg(c4 + 1),
               g2 = __ldg(c4 + 2), g3 = __ldg(c4 + 3);
        float cv[NC] = {g0.x, g0.y, g0.z, g0.w, g1.x, g1.y, g1.z, g1.w,
                        g2.x, g2.y, g2.z, g2.w, g3.x, g3.y, g3.z, g3.w};
        float m[NC - 1];
#pragma unroll
        for (int i = 0; i < NC - 1; i++) m[i] = cv[i] + cv[i + 1];  // exact
#pragma unroll
        for (int e = 0; e < LUT_SIZE / BLOCK; e++) {
            int k = threadIdx.x + e * BLOCK;
            float idxval = (float)(k - 257);
            int count = 0;
#pragma unroll
            for (int i = 0; i < NC - 1; i++) count += (m[i] <= idxval);
            lut[k] = cv[count] * 0.015625f;   // 1/64, exact
        }
    }

    uint64_t pol;
    asm("createpolicy.fractional.L2::evict_last.b64 %0, 1.0;" : "=l"(pol));

    const float4* xg = x + (size_t)blockIdx.x * BLOCK_F4;
    float4* og = out + (size_t)blockIdx.x * BLOCK_F4;
    uint32_t buf_base = (uint32_t)__cvta_generic_to_shared(buf);

    // ---- Prologue: commit all 4 stages (128B/thread in flight) ----
#pragma unroll
    for (int s = 0; s < STAGES; s++) {
        int idx = s * STAGE_F4 + threadIdx.x * 2;       // float4 index
        uint32_t d = buf_base + idx * 16;
        cp16(d, xg + idx, pol);
        cp16(d + 16, xg + idx + 1, pol);
        asm volatile("cp.async.commit_group;" ::: "memory");
    }

    // ---- Discard this block's output lines (skip HBM writeback) ----
    // Block output = 32KB = 256 lines; one per thread.
    {
        char* line = (char*)og + threadIdx.x * 128;
        asm volatile("discard.global.L2 [%0], 128;" :: "l"(line) : "memory");
    }
    __syncthreads();   // all discards (and LUT) done before any store

    const float* lutc = lut + 256;            // +256 folds into LDS imm offset

    // ---- Consume stages; each thread reads only its own copied bytes ----
#define QUANT_ONE(IN, OUT)                                              \
    do {                                                                \
        float u = fminf(fmaxf((IN) * 128.0f, -256.0f), 254.0f);         \
        (OUT) = lutc[__float2int_ru(u)];                                \
    } while (0)

#define DO_STAGE(S, WAIT)                                               \
    do {                                                                \
        cp_wait<WAIT>();                                                \
        int idx = (S) * STAGE_F4 + threadIdx.x * 2;                     \
        float4 a = buf[idx], b = buf[idx + 1];                          \
        float4 ra, rb;                                                  \
        QUANT_ONE(a.x, ra.x); QUANT_ONE(a.y, ra.y);                     \
        QUANT_ONE(a.z, ra.z); QUANT_ONE(a.w, ra.w);                     \
        QUANT_ONE(b.x, rb.x); QUANT_ONE(b.y, rb.y);                     \
        QUANT_ONE(b.z, rb.z); QUANT_ONE(b.w, rb.w);                     \
        stg_256(og + idx, ra, rb);                                      \
    } while (0)

    DO_STAGE(0, 3);
    DO_STAGE(1, 2);
    DO_STAGE(2, 1);
    DO_STAGE(3, 0);
#undef DO_STAGE
#undef QUANT_ONE
}

// Generic tail kernel (unused for this shape; kept for safety).
__global__ void lut_fakequant_tail(const float4* __restrict__ x,
                                   const float* __restrict__ centers,
                                   float4* __restrict__ out,
                                   int start4, int n4) {
    __shared__ float lut[LUT_SIZE];
    if (threadIdx.x < LUT_SIZE) {
        int k = threadIdx.x;
        float idxval = (float)(k - 257);
        int count = 0;
        for (int i = 0; i < NC - 1; i++)
            count += (__ldg(&centers[i]) + __ldg(&centers[i + 1]) <= idxval);
        lut[k] = __ldg(&centers[count]) * 0.015625f;
    }
    __syncthreads();
    int i = start4 + blockIdx.x * blockDim.x + threadIdx.x;
    if (i >= n4) return;
    const float* lutc = lut + 256;
    float4 v = x[i], r;
#define QUANT_ONE(IN, OUT)                                              \
    do {                                                                \
        float u = fminf(fmaxf((IN) * 128.0f, -256.0f), 254.0f);         \
        (OUT) = lutc[__float2int_ru(u)];                                \
    } while (0)
    QUANT_ONE(v.x, r.x); QUANT_ONE(v.y, r.y);
    QUANT_ONE(v.z, r.z); QUANT_ONE(v.w, r.w);
#undef QUANT_ONE
    out[i] = r;
}

extern "C" void kernel_launch(void* const* d_in, const int* in_sizes, int n_in,
                              void* d_out, int out_size) {
    const float* x = (const float*)d_in[0];
    const float* centers = (const float*)d_in[1];
    if (n_in >= 2 && in_sizes[0] == NC && in_sizes[1] != NC) {
        x = (const float*)d_in[1];
        centers = (const float*)d_in[0];
    }

    int n4 = out_size / 4;                    // 3,211,264 float4
    int main_blocks = n4 / BLOCK_F4;          // 1568 exact for this shape

    if (main_blocks > 0)
        lut_fakequant_kernel<<<main_blocks, BLOCK>>>(
            (const float4*)x, centers, (float4*)d_out);

    int done4 = main_blocks * BLOCK_F4;
    int rem4 = n4 - done4;
    if (rem4 > 0)
        lut_fakequant_tail<<<(rem4 + 511) / 512, 512>>>(
            (const float4*)x, centers, (float4*)d_out, done4, n4);
}

// round 15
// speedup vs baseline: 1.2581x; 1.2581x over previous
#include <cuda_runtime.h>

// PytorchLUTFakeQuant: t = clip(x*64, -128, 127); nearest of 16 sorted
// INTEGER centers (tie -> lower index); out = center / 64.
//
// 511-entry shared LUT indexed by ceil(clip(x*128, -256, 254)) + 256.
// (ceil-count identity reproduces argmin lower-index tie-break exactly;
// verified rel_err = 0.)
//
// Round 15: persistent grid-stride over R9's exact inner shape.
//   R9 ran 3136 blocks in 2 launch waves (1776 concurrent): wave
//   transition + 1360 re-prologues + 77% wave-2 fill. Here grid = 1776
//   (= 148 SMs x 12 resident) and each block strides over 1-2 chunks:
//   LUT built once, no wave transition, discards batched up front.
//   Inner loop is byte-identical to R9: 4x front-batched LDG.256 with
//   L2::evict_last, 5-op quant, STG.256 default policy, 40-reg budget.

static constexpr int NC = 16;
static constexpr int LUT_SIZE = 512;
static constexpr int BLOCK = 128;
static constexpr int V8 = 4;                  // float8 per chunk per thread
static constexpr int CHUNK_F8 = BLOCK * V8;   // 512 float8 = 16KB per chunk
static constexpr int MAX_RESIDENT = 148 * 12; // 1776 concurrent blocks

struct float8 { float4 a, b; };

__device__ __forceinline__ float8 ldg_el_256(const float8* p) {
    unsigned r0, r1, r2, r3, r4, r5, r6, r7;
    asm("ld.global.nc.L2::evict_last.v8.b32 {%0,%1,%2,%3,%4,%5,%6,%7}, [%8];"
        : "=r"(r0), "=r"(r1), "=r"(r2), "=r"(r3),
          "=r"(r4), "=r"(r5), "=r"(r6), "=r"(r7)
        : "l"(p));
    float8 v;
    v.a.x = __uint_as_float(r0); v.a.y = __uint_as_float(r1);
    v.a.z = __uint_as_float(r2); v.a.w = __uint_as_float(r3);
    v.b.x = __uint_as_float(r4); v.b.y = __uint_as_float(r5);
    v.b.z = __uint_as_float(r6); v.b.w = __uint_as_float(r7);
    return v;
}

__device__ __forceinline__ void stg_256(float8* p, float4 a, float4 b) {
    asm volatile("st.global.v8.b32 [%0], {%1,%2,%3,%4,%5,%6,%7,%8};"
                 :: "l"(p),
                    "r"(__float_as_uint(a.x)), "r"(__float_as_uint(a.y)),
                    "r"(__float_as_uint(a.z)), "r"(__float_as_uint(a.w)),
                    "r"(__float_as_uint(b.x)), "r"(__float_as_uint(b.y)),
                    "r"(__float_as_uint(b.z)), "r"(__float_as_uint(b.w))
                 : "memory");
}

__global__ void __launch_bounds__(BLOCK, 12)
lut_fakequant_kernel(const float8* __restrict__ x,
                     const float* __restrict__ centers,
                     float8* __restrict__ out,
                     int nchunks) {
    __shared__ float lut[LUT_SIZE];

    // ---- Build LUT once per block: lut[k] = cv[ #{ m_i <= k-257 } ]/64 ----
    {
        const float4* c4 = (const float4*)centers;
        float4 g0 = __ldg(c4 + 0), g1 = __ldg(c4 + 1),
               g2 = __ldg(c4 + 2), g3 = __ldg(c4 + 3);
        float cv[NC] = {g0.x, g0.y, g0.z, g0.w, g1.x, g1.y, g1.z, g1.w,
                        g2.x, g2.y, g2.z, g2.w, g3.x, g3.y, g3.z, g3.w};
        float m[NC - 1];
#pragma unroll
        for (int i = 0; i < NC - 1; i++) m[i] = cv[i] + cv[i + 1];  // exact
#pragma unroll
        for (int e = 0; e < LUT_SIZE / BLOCK; e++) {
            int k = threadIdx.x + e * BLOCK;
            float idxval = (float)(k - 257);
            int count = 0;
#pragma unroll
            for (int i = 0; i < NC - 1; i++) count += (m[i] <= idxval);
            lut[k] = cv[count] * 0.015625f;   // 1/64, exact
        }
    }

    // ---- Discard ALL owned chunks' output lines up front ----
    // Chunk = 16KB = 128 lines; one line per thread per owned chunk.
    for (int c = blockIdx.x; c < nchunks; c += gridDim.x) {
        char* line = (char*)(out + (size_t)c * CHUNK_F8) + threadIdx.x * 128;
        asm volatile("discard.global.L2 [%0], 128;" :: "l"(line) : "memory");
    }
    // One barrier: orders LUT build + all discards before any store.
    __syncthreads();

    const float* lutc = lut + 256;            // +256 folds into LDS imm offset

    // ---- Persistent loop over chunks (1-2 per block) ----
    for (int c = blockIdx.x; c < nchunks; c += gridDim.x) {
        int base8 = c * CHUNK_F8 + threadIdx.x;

        // R9 inner shape: 4 front-batched LDG.256 (128B in flight).
        float8 v[V8];
#pragma unroll
        for (int k = 0; k < V8; k++)
            v[k] = ldg_el_256(&x[base8 + k * BLOCK]);

#pragma unroll
        for (int k = 0; k < V8; k++) {
            float4 ra, rb;
            // FMUL, FMNMX, FMNMX, F2I.RU, LDS. Clamp [-256,254] exact:
            // spec clips t at -128 -> u >= -256 -> index 0 is correct.
#define QUANT_ONE(IN, OUT)                                              \
            do {                                                        \
                float u = fminf(fmaxf((IN) * 128.0f, -256.0f), 254.0f); \
                (OUT) = lutc[__float2int_ru(u)];                        \
            } while (0)
            QUANT_ONE(v[k].a.x, ra.x); QUANT_ONE(v[k].a.y, ra.y);
            QUANT_ONE(v[k].a.z, ra.z); QUANT_ONE(v[k].a.w, ra.w);
            QUANT_ONE(v[k].b.x, rb.x); QUANT_ONE(v[k].b.y, rb.y);
            QUANT_ONE(v[k].b.z, rb.z); QUANT_ONE(v[k].b.w, rb.w);
#undef QUANT_ONE
            stg_256(&out[base8 + k * BLOCK], ra, rb);
        }
    }
}

// Generic tail kernel (unused for this shape; kept for safety).
__global__ void lut_fakequant_tail(const float4* __restrict__ x,
                                   const float* __restrict__ centers,
                                   float4* __restrict__ out,
                                   int start4, int n4) {
    __shared__ float lut[LUT_SIZE];
    if (threadIdx.x < LUT_SIZE) {
        int k = threadIdx.x;
        float idxval = (float)(k - 257);
        int count = 0;
        for (int i = 0; i < NC - 1; i++)
            count += (__ldg(&centers[i]) + __ldg(&centers[i + 1]) <= idxval);
        lut[k] = __ldg(&centers[count]) * 0.015625f;
    }
    __syncthreads();
    int i = start4 + blockIdx.x * blockDim.x + threadIdx.x;
    if (i >= n4) return;
    const float* lutc = lut + 256;
    float4 v = x[i], r;
#define QUANT_ONE(IN, OUT)                                              \
    do {                                                                \
        float u = fminf(fmaxf((IN) * 128.0f, -256.0f), 254.0f);         \
        (OUT) = lutc[__float2int_ru(u)];                                \
    } while (0)
    QUANT_ONE(v.x, r.x); QUANT_ONE(v.y, r.y);
    QUANT_ONE(v.z, r.z); QUANT_ONE(v.w, r.w);
#undef QUANT_ONE
    out[i] = r;
}

extern "C" void kernel_launch(void* const* d_in, const int* in_sizes, int n_in,
                              void* d_out, int out_size) {
    const float* x = (const float*)d_in[0];
    const float* centers = (const float*)d_in[1];
    if (n_in >= 2 && in_sizes[0] == NC && in_sizes[1] != NC) {
        x = (const float*)d_in[1];
        centers = (const float*)d_in[0];
    }

    int n8 = out_size / 8;                    // 1,605,632 float8 (exact)
    int nchunks = n8 / CHUNK_F8;              // 3136 exact for this shape
    int grid = nchunks < MAX_RESIDENT ? nchunks : MAX_RESIDENT;  // 1776

    if (nchunks > 0)
        lut_fakequant_kernel<<<grid, BLOCK>>>(
            (const float8*)x, centers, (float8*)d_out, nchunks);

    int done4 = nchunks * CHUNK_F8 * 2;
    int n4 = out_size / 4;
    int rem4 = n4 - done4;
    if (rem4 > 0)
        lut_fakequant_tail<<<(rem4 + 511) / 512, 512>>>(
            (const float4*)x, centers, (float4*)d_out, done4, n4);
}